// round 1
// baseline (speedup 1.0000x reference)
#include <cuda_runtime.h>

// ---------------- problem constants ----------------
#define K_CODES 512
#define D_DIM   64
#define NPTS    65536          // 64*32*32
#define HW      1024           // 32*32
#define CHW     65536          // 64*1024
#define BETA_C  0.25f
#define DECAY_C 0.99f
#define OMD_C   0.01f          // 1 - decay
#define EPS_C   1e-5f

// output layout (float32, tuple order):
// [0] loss | [1 .. 1+4194304) out_q NCHW | perplexity | idx (65536) |
// new_cs (512) | new_ema_w (32768) | new_embedding (32768)
#define OFF_Q    1
#define OFF_PERP 4194305
#define OFF_IDX  4194306
#define OFF_CS   4259842
#define OFF_W    4260354
#define OFF_E    4293122

// ---------------- scratch (no allocations allowed) ----------------
__device__ float g_counts[K_CODES];
__device__ float g_dw[K_CODES * D_DIM];
__device__ float g_loss_acc;

// ---------------- f32x2 helpers (sm_103a packed fp32) ----------------
__device__ __forceinline__ unsigned long long fma2(unsigned long long a,
                                                   unsigned long long b,
                                                   unsigned long long c) {
    unsigned long long d;
    asm("fma.rn.f32x2 %0, %1, %2, %3;" : "=l"(d) : "l"(a), "l"(b), "l"(c));
    return d;
}
__device__ __forceinline__ unsigned long long add2(unsigned long long a,
                                                   unsigned long long b) {
    unsigned long long d;
    asm("add.rn.f32x2 %0, %1, %2;" : "=l"(d) : "l"(a), "l"(b));
    return d;
}
__device__ __forceinline__ unsigned long long pack2(float lo, float hi) {
    unsigned long long d;
    asm("mov.b64 %0, {%1, %2};" : "=l"(d) : "f"(lo), "f"(hi));
    return d;
}
__device__ __forceinline__ void unpack2(unsigned long long v, float& lo, float& hi) {
    asm("mov.b64 {%0, %1}, %2;" : "=f"(lo), "=f"(hi) : "l"(v));
}

// ---------------- kernel 0: zero scratch ----------------
__global__ void vq_zero_kernel() {
    int i = blockIdx.x * blockDim.x + threadIdx.x;
    if (i < K_CODES * D_DIM) g_dw[i] = 0.0f;
    if (i < K_CODES)         g_counts[i] = 0.0f;
    if (i == 0)              g_loss_acc = 0.0f;
}

// ---------------- kernel 1: argmin + quantize + segment sums ----------------
// grid = 128 CTAs x 512 threads = 65536 threads, one point each.
// smem: embedding [512][64] f32 (128KB) + row norms [512] (2KB)
__global__ __launch_bounds__(512, 1)
void vq_main_kernel(const float* __restrict__ in,     // [64,64,32,32] NCHW
                    const float* __restrict__ emb,    // [512,64]
                    float* __restrict__ out_q,        // NCHW view at out+1
                    float* __restrict__ out_idx) {    // [65536] as float
    extern __shared__ float sm[];
    float* e_sh = sm;                        // 32768 floats
    float* nrm  = sm + K_CODES * D_DIM;      // 512 floats

    const int tid = threadIdx.x;

    // cooperative load of embedding into shared (float4)
    {
        const float4* src = (const float4*)emb;
        float4*       dst = (float4*)e_sh;
        #pragma unroll
        for (int i = tid; i < (K_CODES * D_DIM) / 4; i += 512) dst[i] = src[i];
    }
    __syncthreads();

    // per-row norms; rotate start channel by thread to avoid 32-way bank conflicts
    {
        const float* row = e_sh + tid * D_DIM;
        const int r = tid & 63;
        float s = 0.0f;
        #pragma unroll
        for (int j = 0; j < D_DIM; ++j) {
            int c = (j + r) & 63;
            float v = row[c];
            s = fmaf(v, v, s);
        }
        nrm[tid] = s;
    }
    __syncthreads();

    const int p  = blockIdx.x * 512 + tid;   // 0..65535 exactly
    const int b  = p >> 10;
    const int hw = p & 1023;
    const float* xin = in + b * CHW + hw;

    // load x (64 channels, stride HW, coalesced across lanes), pack pairs
    unsigned long long xp[32];
    #pragma unroll
    for (int c = 0; c < D_DIM; c += 2) {
        float a0 = xin[c * HW];
        float a1 = xin[(c + 1) * HW];
        xp[c >> 1] = pack2(a0, a1);
    }

    // argmin over codes: metric = |e|^2 - 2 x.e   (x^2 dropped; monotonic)
    int   best  = 0;
    float bestd = 3.4e38f;
    #pragma unroll 1
    for (int k = 0; k < K_CODES; ++k) {
        const ulonglong2* row = (const ulonglong2*)(e_sh + (k << 6));
        unsigned long long a0 = 0ull, a1 = 0ull, a2 = 0ull, a3 = 0ull;
        #pragma unroll
        for (int j = 0; j < 16; j += 4) {
            ulonglong2 v0 = row[j + 0];
            ulonglong2 v1 = row[j + 1];
            ulonglong2 v2 = row[j + 2];
            ulonglong2 v3 = row[j + 3];
            a0 = fma2(xp[2 * j + 0], v0.x, a0);
            a1 = fma2(xp[2 * j + 1], v0.y, a1);
            a2 = fma2(xp[2 * j + 2], v1.x, a2);
            a3 = fma2(xp[2 * j + 3], v1.y, a3);
            a0 = fma2(xp[2 * j + 4], v2.x, a0);
            a1 = fma2(xp[2 * j + 5], v2.y, a1);
            a2 = fma2(xp[2 * j + 6], v3.x, a2);
            a3 = fma2(xp[2 * j + 7], v3.y, a3);
        }
        a0 = add2(a0, a1);
        a2 = add2(a2, a3);
        a0 = add2(a0, a2);
        float dl, dh;
        unpack2(a0, dl, dh);
        float dot  = dl + dh;
        float dist = fmaf(-2.0f, dot, nrm[k]);
        if (dist < bestd) { bestd = dist; best = k; }
    }

    out_idx[p] = (float)best;

    // epilogue: gather e[best] from GLOBAL (L2-hot, conflict-free),
    // write quantized_st (NCHW), accumulate loss + segment sums
    const float4* erow  = (const float4*)(emb + best * D_DIM);
    float*        qout  = out_q + b * CHW + hw;
    float*        dwrow = g_dw + best * D_DIM;
    float lsum = 0.0f;
    #pragma unroll
    for (int j = 0; j < 16; ++j) {
        float4 e4 = __ldg(erow + j);
        float x0, x1, x2v, x3v;
        unpack2(xp[2 * j + 0], x0, x1);
        unpack2(xp[2 * j + 1], x2v, x3v);
        const int c = 4 * j;
        float d0 = e4.x - x0;
        float d1 = e4.y - x1;
        float d2 = e4.z - x2v;
        float d3 = e4.w - x3v;
        // quantized_st = x + (q - x), replicated exactly
        qout[(c + 0) * HW] = x0  + d0;
        qout[(c + 1) * HW] = x1  + d1;
        qout[(c + 2) * HW] = x2v + d2;
        qout[(c + 3) * HW] = x3v + d3;
        lsum = fmaf(d0, d0, lsum);
        lsum = fmaf(d1, d1, lsum);
        lsum = fmaf(d2, d2, lsum);
        lsum = fmaf(d3, d3, lsum);
        atomicAdd(dwrow + c + 0, x0);
        atomicAdd(dwrow + c + 1, x1);
        atomicAdd(dwrow + c + 2, x2v);
        atomicAdd(dwrow + c + 3, x3v);
    }
    // warp-reduce loss then one atomic per warp
    #pragma unroll
    for (int o = 16; o > 0; o >>= 1) lsum += __shfl_xor_sync(0xFFFFFFFFu, lsum, o);
    if ((tid & 31) == 0) atomicAdd(&g_loss_acc, lsum);
    atomicAdd(&g_counts[best], 1.0f);
}

// ---------------- kernel 2: finalize (EMA update, smoothing, scalars) ----------------
__global__ __launch_bounds__(512, 1)
void vq_finalize_kernel(const float* __restrict__ ema_w,
                        const float* __restrict__ ema_cs,
                        float* __restrict__ out) {
    __shared__ float red[K_CODES];
    __shared__ float s_cs[K_CODES];
    const int k = threadIdx.x;

    const float cnt = g_counts[k];
    const float raw = ema_cs[k] * DECAY_C + OMD_C * cnt;

    red[k] = raw;
    __syncthreads();
    #pragma unroll
    for (int o = 256; o > 0; o >>= 1) {
        if (k < o) red[k] += red[k + o];
        __syncthreads();
    }
    const float n = red[0];
    __syncthreads();

    const float ncs = (raw + EPS_C) / (n + (float)K_CODES * EPS_C) * n;
    s_cs[k] = ncs;
    out[OFF_CS + k] = ncs;

    // perplexity: exp(-sum p*log(p+1e-10))
    const float pprob = cnt * (1.0f / (float)NPTS);
    red[k] = pprob * logf(pprob + 1e-10f);
    __syncthreads();
    #pragma unroll
    for (int o = 256; o > 0; o >>= 1) {
        if (k < o) red[k] += red[k + o];
        __syncthreads();
    }
    if (k == 0) {
        out[OFF_PERP] = expf(-red[0]);
        out[0] = BETA_C * g_loss_acc / (float)(NPTS * D_DIM);
    }
    __syncthreads();   // s_cs ready for all

    #pragma unroll
    for (int i = k; i < K_CODES * D_DIM; i += K_CODES) {
        float w = ema_w[i] * DECAY_C + OMD_C * g_dw[i];
        out[OFF_W + i] = w;
        out[OFF_E + i] = w / s_cs[i >> 6];
    }
}

// ---------------- launch ----------------
extern "C" void kernel_launch(void* const* d_in, const int* in_sizes, int n_in,
                              void* d_out, int out_size) {
    const float* in     = (const float*)d_in[0];  // inputs  [64,64,32,32]
    const float* emb    = (const float*)d_in[1];  // embedding [512,64]
    const float* ema_w  = (const float*)d_in[2];  // ema_w [512,64]
    const float* ema_cs = (const float*)d_in[3];  // ema_cluster_size [512]
    float* out = (float*)d_out;

    const int smem_bytes = (K_CODES * D_DIM + K_CODES) * (int)sizeof(float); // 133120
    cudaFuncSetAttribute(vq_main_kernel,
                         cudaFuncAttributeMaxDynamicSharedMemorySize, smem_bytes);

    vq_zero_kernel<<<128, 256>>>();
    vq_main_kernel<<<128, 512, smem_bytes>>>(in, emb, out + OFF_Q, out + OFF_IDX);
    vq_finalize_kernel<<<1, 512>>>(ema_w, ema_cs, out);
}

// round 3
// speedup vs baseline: 1.4257x; 1.4257x over previous
#include <cuda_runtime.h>

// ---------------- problem constants ----------------
#define K_CODES 512
#define D_DIM   64
#define NPTS    65536          // 64*32*32
#define HW      1024           // 32*32
#define CHW     65536          // 64*1024
#define BETA_C  0.25f
#define DECAY_C 0.99f
#define OMD_C   0.01f          // 1 - decay
#define EPS_C   1e-5f

// output layout (float32, tuple order):
// [0] loss | [1 .. 1+4194304) out_q NCHW | perplexity | idx (65536) |
// new_cs (512) | new_ema_w (32768) | new_embedding (32768)
#define OFF_Q    1
#define OFF_PERP 4194305
#define OFF_IDX  4194306
#define OFF_CS   4259842
#define OFF_W    4260354
#define OFF_E    4293122

// ---------------- scratch (zero-initialized at load; kernels restore zero) ----
__device__ float g_counts[K_CODES];
__device__ float g_dw[K_CODES * D_DIM];
__device__ float g_ncs[K_CODES];
__device__ float g_loss_acc;

// ---------------- f32x2 helpers (sm_103a packed fp32) ----------------
__device__ __forceinline__ unsigned long long fma2(unsigned long long a,
                                                   unsigned long long b,
                                                   unsigned long long c) {
    unsigned long long d;
    asm("fma.rn.f32x2 %0, %1, %2, %3;" : "=l"(d) : "l"(a), "l"(b), "l"(c));
    return d;
}
__device__ __forceinline__ unsigned long long add2(unsigned long long a,
                                                   unsigned long long b) {
    unsigned long long d;
    asm("add.rn.f32x2 %0, %1, %2;" : "=l"(d) : "l"(a), "l"(b));
    return d;
}
__device__ __forceinline__ unsigned long long pack2(float lo, float hi) {
    unsigned long long d;
    asm("mov.b64 %0, {%1, %2};" : "=l"(d) : "f"(lo), "f"(hi));
    return d;
}
__device__ __forceinline__ void unpack2(unsigned long long v, float& lo, float& hi) {
    asm("mov.b64 {%0, %1}, %2;" : "=f"(lo), "=f"(hi) : "l"(v));
}
// vector f32 global reduction (sm_90+): 1 instruction for 4 atomic adds
__device__ __forceinline__ void red_add_v4(float* p, float a, float b, float c, float d) {
    asm volatile("red.global.add.v4.f32 [%0], {%1, %2, %3, %4};"
                 :: "l"(p), "f"(a), "f"(b), "f"(c), "f"(d) : "memory");
}

// ---------------- kernel 1: argmin + quantize + segment sums ----------------
// 128 CTAs x 512 threads = 65536 threads, one point each. 1 CTA/SM.
// smem: embedding [512][64] f32 (128KB) + row norms [512] (2KB)
__global__ __launch_bounds__(512, 1)
void vq_main_kernel(const float* __restrict__ in,     // [64,64,32,32] NCHW
                    const float* __restrict__ emb,    // [512,64]
                    float* __restrict__ out_q,        // NCHW view at out+OFF_Q
                    float* __restrict__ out_idx) {    // [65536] as float
    extern __shared__ float sm[];
    float* e_sh = sm;                        // 32768 floats
    float* nrm  = sm + K_CODES * D_DIM;      // 512 floats

    const int tid = threadIdx.x;

    // cooperative load of embedding into shared (float4)
    {
        const float4* src = (const float4*)emb;
        float4*       dst = (float4*)e_sh;
        for (int i = tid; i < (K_CODES * D_DIM) / 4; i += 512) dst[i] = src[i];
    }
    __syncthreads();

    // per-row norms; rotate start channel to avoid 32-way bank conflicts
    {
        const float* row = e_sh + tid * D_DIM;
        const int r = tid & 63;
        float s = 0.0f;
        #pragma unroll
        for (int j = 0; j < D_DIM; ++j) {
            int c = (j + r) & 63;
            float v = row[c];
            s = fmaf(v, v, s);
        }
        nrm[tid] = s;
    }
    __syncthreads();

    const int p  = blockIdx.x * 512 + tid;   // 0..65535 exactly
    const int b  = p >> 10;
    const int hw = p & 1023;
    const float* xin = in + b * CHW + hw;

    // load x (64 channels, stride HW, coalesced across lanes), pack pairs
    unsigned long long xp[32];
    #pragma unroll
    for (int c = 0; c < D_DIM; c += 2)
        xp[c >> 1] = pack2(xin[c * HW], xin[(c + 1) * HW]);

    // |x|^2 (used for exact loss: |x-e|^2 = bestd + |x|^2)
    float xnorm;
    {
        unsigned long long n0 = 0ull, n1 = 0ull;
        #pragma unroll
        for (int j = 0; j < 32; j += 2) {
            n0 = fma2(xp[j],     xp[j],     n0);
            n1 = fma2(xp[j + 1], xp[j + 1], n1);
        }
        n0 = add2(n0, n1);
        float xl, xh; unpack2(n0, xl, xh);
        xnorm = xl + xh;
    }

    // argmin over codes: metric = |e|^2 - 2 x.e   (x^2 dropped; monotonic)
    // one code row = 64 floats = 16 ulonglong2
    int   best  = 0;
    float bestd = 3.4e38f;
    const ulonglong2* ebase = (const ulonglong2*)e_sh;
    #pragma unroll 1
    for (int k = 0; k < K_CODES; ++k) {
        const ulonglong2* row = ebase + (k << 4);   // 16 ulonglong2 per row
        unsigned long long a0 = 0ull, a1 = 0ull, a2 = 0ull;
        #pragma unroll
        for (int g = 0; g < 4; ++g) {
            ulonglong2 v0 = row[4 * g + 0];
            ulonglong2 v1 = row[4 * g + 1];
            ulonglong2 v2 = row[4 * g + 2];
            ulonglong2 v3 = row[4 * g + 3];
            a0 = fma2(xp[8 * g + 0], v0.x, a0);
            a1 = fma2(xp[8 * g + 1], v0.y, a1);
            a2 = fma2(xp[8 * g + 2], v1.x, a2);
            a0 = fma2(xp[8 * g + 3], v1.y, a0);
            a1 = fma2(xp[8 * g + 4], v2.x, a1);
            a2 = fma2(xp[8 * g + 5], v2.y, a2);
            a0 = fma2(xp[8 * g + 6], v3.x, a0);
            a1 = fma2(xp[8 * g + 7], v3.y, a1);
        }
        a0 = add2(a0, a1);
        a0 = add2(a0, a2);
        float dl, dh; unpack2(a0, dl, dh);
        float dist = fmaf(-2.0f, dl + dh, nrm[k]);
        if (dist < bestd) { bestd = dist; best = k; }
    }

    out_idx[p] = (float)best;

    // loss: |x - e_best|^2 == bestd + |x|^2 (analytically exact); warp-reduce
    {
        float l = bestd + xnorm;
        #pragma unroll
        for (int o = 16; o > 0; o >>= 1) l += __shfl_xor_sync(0xFFFFFFFFu, l, o);
        if ((tid & 31) == 0) atomicAdd(&g_loss_acc, l);
    }
    atomicAdd(&g_counts[best], 1.0f);

    // epilogue: gather e[best] from GLOBAL (L2-hot, no smem bank conflicts),
    // write quantized_st (NCHW, coalesced), accumulate dw with vector atomics
    const float4* erow  = (const float4*)(emb + best * D_DIM);
    float*        qout  = out_q + b * CHW + hw;
    float*        dwrow = g_dw + best * D_DIM;
    #pragma unroll
    for (int j = 0; j < 16; ++j) {
        float4 e4 = __ldg(erow + j);
        float x0, x1, x2v, x3v;
        unpack2(xp[2 * j + 0], x0, x1);
        unpack2(xp[2 * j + 1], x2v, x3v);
        const int c = 4 * j;
        // quantized_st = x + (q - x), replicated exactly
        qout[(c + 0) * HW] = x0  + (e4.x - x0);
        qout[(c + 1) * HW] = x1  + (e4.y - x1);
        qout[(c + 2) * HW] = x2v + (e4.z - x2v);
        qout[(c + 3) * HW] = x3v + (e4.w - x3v);
        red_add_v4(dwrow + c, x0, x1, x2v, x3v);
    }
}

// ---------------- kernel 2a: single-CTA reductions + scalars ----------------
__global__ __launch_bounds__(512, 1)
void vq_finA_kernel(const float* __restrict__ ema_cs,
                    float* __restrict__ out) {
    __shared__ float red[K_CODES];
    const int k = threadIdx.x;

    const float cnt = g_counts[k];
    const float raw = ema_cs[k] * DECAY_C + OMD_C * cnt;

    red[k] = raw;
    __syncthreads();
    #pragma unroll
    for (int o = 256; o > 0; o >>= 1) {
        if (k < o) red[k] += red[k + o];
        __syncthreads();
    }
    const float n = red[0];
    __syncthreads();

    const float ncs = (raw + EPS_C) / (n + (float)K_CODES * EPS_C) * n;
    g_ncs[k] = ncs;
    out[OFF_CS + k] = ncs;

    // perplexity: exp(-sum p*log(p+1e-10))
    const float pprob = cnt * (1.0f / (float)NPTS);
    red[k] = pprob * logf(pprob + 1e-10f);
    __syncthreads();
    #pragma unroll
    for (int o = 256; o > 0; o >>= 1) {
        if (k < o) red[k] += red[k + o];
        __syncthreads();
    }
    if (k == 0) {
        out[OFF_PERP] = expf(-red[0]);
        out[0] = BETA_C * g_loss_acc / (float)(NPTS * D_DIM);
        g_loss_acc = 0.0f;                 // restore zero invariant
    }
    g_counts[k] = 0.0f;                    // restore zero invariant
}

// ---------------- kernel 2b: parallel EMA-w / new-embedding ----------------
__global__ __launch_bounds__(512, 1)
void vq_finB_kernel(const float* __restrict__ ema_w,
                    float* __restrict__ out) {
    const int i = blockIdx.x * 512 + threadIdx.x;   // < 32768 exactly
    const float w = ema_w[i] * DECAY_C + OMD_C * g_dw[i];
    g_dw[i] = 0.0f;                        // restore zero invariant
    out[OFF_W + i] = w;
    out[OFF_E + i] = w / g_ncs[i >> 6];
}

// ---------------- launch ----------------
extern "C" void kernel_launch(void* const* d_in, const int* in_sizes, int n_in,
                              void* d_out, int out_size) {
    const float* in     = (const float*)d_in[0];  // inputs  [64,64,32,32]
    const float* emb    = (const float*)d_in[1];  // embedding [512,64]
    const float* ema_w  = (const float*)d_in[2];  // ema_w [512,64]
    const float* ema_cs = (const float*)d_in[3];  // ema_cluster_size [512]
    float* out = (float*)d_out;

    const int smem_bytes = (K_CODES * D_DIM + K_CODES) * (int)sizeof(float); // 133120
    cudaFuncSetAttribute(vq_main_kernel,
                         cudaFuncAttributeMaxDynamicSharedMemorySize, smem_bytes);

    vq_main_kernel<<<128, 512, smem_bytes>>>(in, emb, out + OFF_Q, out + OFF_IDX);
    vq_finA_kernel<<<1, 512>>>(ema_cs, out);
    vq_finB_kernel<<<64, 512>>>(ema_w, out);
}